// round 12
// baseline (speedup 1.0000x reference)
#include <cuda_runtime.h>
#include <cuda_bf16.h>
#include <cstdint>

static constexpr int BDIM = 4096;
static constexpr int IDIM = 1024;
static constexpr int HDIM = 2048;
static constexpr int NSTEPS = 10;
static constexpr float DT = 0.1f;

static constexpr int BM = 128, BN = 64, BK = 32;
static constexpr int NT = 256;
// stage: [A_hi 8K | A_lo 8K | B_hi 4K | B_lo 4K] = 24 KB, 2 stages
static constexpr int A_PLANE = BM * BK * 2;            // 8 KB
static constexpr int B_PLANE = BN * BK * 2;            // 4 KB
static constexpr int STAGE_BYTES = 2 * A_PLANE + 2 * B_PLANE;   // 24 KB
static constexpr int OFF_BPL = 2 * A_PLANE;            // 16 KB into stage
static constexpr int OFF_COLV = 2 * STAGE_BYTES;       // 48 KB
static constexpr int SMEM_TOTAL = OFF_COLV + BN * 4 + 16;   // ~48.3 KB -> 4 CTAs/SM

__device__ float g_ihb  [BDIM * HDIM];
__device__ float g_hfull[BDIM * HDIM];
__device__ __nv_bfloat16 g_hhiA[BDIM * HDIM];
__device__ __nv_bfloat16 g_hloA[BDIM * HDIM];
__device__ __nv_bfloat16 g_hhiB[BDIM * HDIM];
__device__ __nv_bfloat16 g_hloB[BDIM * HDIM];
__device__ __nv_bfloat16 g_xhi [BDIM * IDIM];
__device__ __nv_bfloat16 g_xlo [BDIM * IDIM];
__device__ __nv_bfloat16 g_wihhi[HDIM * IDIM];
__device__ __nv_bfloat16 g_wihlo[HDIM * IDIM];
__device__ __nv_bfloat16 g_whhhi[HDIM * HDIM];
__device__ __nv_bfloat16 g_whhlo[HDIM * HDIM];

__device__ __forceinline__ uint32_t smem_u32(const void* p) {
    uint32_t a;
    asm("{ .reg .u64 t; cvta.to.shared.u64 t, %1; cvt.u32.u64 %0, t; }" : "=r"(a) : "l"(p));
    return a;
}
__device__ __forceinline__ void cp16(uint32_t dst, const void* src) {
    asm volatile("cp.async.cg.shared.global [%0], [%1], 16;" :: "r"(dst), "l"(src) : "memory");
}
__device__ __forceinline__ void cp_commit() { asm volatile("cp.async.commit_group;" ::: "memory"); }
template <int N> __device__ __forceinline__ void cp_wait() {
    asm volatile("cp.async.wait_group %0;" :: "n"(N) : "memory");
}
__device__ __forceinline__ float tanh_acc(float x) {
    float ax = fabsf(x);
    float e = __expf(-2.0f * ax);
    float t = (1.0f - e) / (1.0f + e);
    return copysignf(t, x);
}
__device__ __forceinline__ void mma_bf16(float* c, const uint32_t* a, const uint32_t* b) {
    asm volatile(
        "mma.sync.aligned.m16n8k16.row.col.f32.bf16.bf16.f32 "
        "{%0,%1,%2,%3},{%4,%5,%6,%7},{%8,%9},{%0,%1,%2,%3};"
        : "+f"(c[0]), "+f"(c[1]), "+f"(c[2]), "+f"(c[3])
        : "r"(a[0]), "r"(a[1]), "r"(a[2]), "r"(a[3]), "r"(b[0]), "r"(b[1]));
}
__device__ __forceinline__ void ldsm4(uint32_t* r, uint32_t addr) {
    asm volatile("ldmatrix.sync.aligned.m8n8.x4.shared.b16 {%0,%1,%2,%3}, [%4];"
                 : "=r"(r[0]), "=r"(r[1]), "=r"(r[2]), "=r"(r[3]) : "r"(addr));
}
__device__ __forceinline__ void split1(float v, __nv_bfloat16& h, __nv_bfloat16& l) {
    h = __float2bfloat16(v);
    l = __float2bfloat16(v - __bfloat162float(h));
}

// One prep kernel: split x / Wih / Whh, copy+split h0.
__global__ void prep_all_kernel(const float* __restrict__ x,
                                const float* __restrict__ Wih,
                                const float* __restrict__ Whh,
                                const float* __restrict__ h0,
                                __nv_bfloat16* __restrict__ xhi, __nv_bfloat16* __restrict__ xlo,
                                __nv_bfloat16* __restrict__ wihhi, __nv_bfloat16* __restrict__ wihlo,
                                __nv_bfloat16* __restrict__ whhhi, __nv_bfloat16* __restrict__ whhlo,
                                float* __restrict__ hfull,
                                __nv_bfloat16* __restrict__ hhi, __nv_bfloat16* __restrict__ hlo) {
    const int stride = gridDim.x * blockDim.x;
    const int t0 = blockIdx.x * blockDim.x + threadIdx.x;
    auto split4 = [](float4 v, __nv_bfloat16* hi, __nv_bfloat16* lo, int i) {
        __nv_bfloat162 h01, h23, l01, l23;
        split1(v.x, h01.x, l01.x); split1(v.y, h01.y, l01.y);
        split1(v.z, h23.x, l23.x); split1(v.w, h23.y, l23.y);
        reinterpret_cast<__nv_bfloat162*>(hi)[i * 2]     = h01;
        reinterpret_cast<__nv_bfloat162*>(hi)[i * 2 + 1] = h23;
        reinterpret_cast<__nv_bfloat162*>(lo)[i * 2]     = l01;
        reinterpret_cast<__nv_bfloat162*>(lo)[i * 2 + 1] = l23;
    };
    for (int i = t0; i < BDIM * IDIM / 4; i += stride)
        split4(reinterpret_cast<const float4*>(x)[i], xhi, xlo, i);
    for (int i = t0; i < HDIM * IDIM / 4; i += stride)
        split4(reinterpret_cast<const float4*>(Wih)[i], wihhi, wihlo, i);
    for (int i = t0; i < HDIM * HDIM / 4; i += stride)
        split4(reinterpret_cast<const float4*>(Whh)[i], whhhi, whhlo, i);
    for (int i = t0; i < BDIM * HDIM / 4; i += stride) {
        float4 v = reinterpret_cast<const float4*>(h0)[i];
        reinterpret_cast<float4*>(hfull)[i] = v;
        split4(v, hhi, hlo, i);
    }
}

// D[m][n] = sum_k A[m][k]*W[n][k]; bf16x3 (hh + hl + lh), fp32 acc.
template <bool STEP>
__global__ __launch_bounds__(NT, 4)
void gemm_kernel(const __nv_bfloat16* __restrict__ Ahi, const __nv_bfloat16* __restrict__ Alo,
                 const __nv_bfloat16* __restrict__ Whi, const __nv_bfloat16* __restrict__ Wlo,
                 int K,
                 const float* __restrict__ aux0,   // STEP: ihb      | !STEP: b_ih
                 const float* __restrict__ aux1,   // STEP: hfull_in | !STEP: b_hh
                 const float* __restrict__ tau,
                 float* __restrict__ out_full,
                 __nv_bfloat16* __restrict__ out_hi, __nv_bfloat16* __restrict__ out_lo,
                 int ldo) {
    extern __shared__ char sm[];
    float* colv = (float*)(sm + OFF_COLV);
    const uint32_t sb = smem_u32(sm);
    const int tid = threadIdx.x;
    const int lane = tid & 31;
    const int wid = tid >> 5;
    const int wm = wid >> 2;      // 0..1
    const int wn = wid & 3;       // 0..3
    const int g = lane >> 2;
    const int tig = lane & 3;
    const int n0 = blockIdx.x * BN;
    const int m0 = blockIdx.y * BM;

    for (int j = tid; j < BN; j += NT)
        colv[j] = STEP ? __expf(-DT / tau[n0 + j]) : (aux0[n0 + j] + aux1[n0 + j]);

    // ---- compact staging geometry: sr = tid>>2 (row), sj = tid&3 (16B quad) ----
    const int sj = tid & 3;
    const int sr = tid >> 2;                     // 0..63
    const uint32_t sd = (uint32_t)(sr * 64 + ((sj ^ ((sr >> 1) & 3)) << 4));
    const size_t rowskip = (size_t)64 * K * 2;   // 64 rows, bytes
    const char* aHi = (const char*)Ahi + ((size_t)(m0 + sr) * K + sj * 8) * 2;
    const char* aLo = (const char*)Alo + ((size_t)(m0 + sr) * K + sj * 8) * 2;
    const char* bHi = (const char*)Whi + ((size_t)(n0 + sr) * K + sj * 8) * 2;
    const char* bLo = (const char*)Wlo + ((size_t)(n0 + sr) * K + sj * 8) * 2;

    auto stage = [&](int i, uint32_t base) {
        const size_t koff = (size_t)i * (BK * 2);
        cp16(base + sd,                   aHi + koff);
        cp16(base + sd + 4096,            aHi + rowskip + koff);
        cp16(base + A_PLANE + sd,         aLo + koff);
        cp16(base + A_PLANE + sd + 4096,  aLo + rowskip + koff);
        cp16(base + OFF_BPL + sd,             bHi + koff);
        cp16(base + OFF_BPL + B_PLANE + sd,   bLo + koff);
    };

    // ---- ldmatrix geometry: computed bases, offsets by arithmetic ----
    const int lrow = ((lane >> 3) & 1) * 8 + (lane & 7);
    const int lkh  = (lane >> 4);
    uint32_t aO, bO;
    {
        const int rA = wm * 64 + lrow;
        aO = (uint32_t)(rA * 64 + ((lkh ^ ((rA >> 1) & 3)) << 4));
        const int rB = wn * 16 + lrow;
        bO = (uint32_t)(OFF_BPL + rB * 64 + ((lkh ^ ((rB >> 1) & 3)) << 4));
    }

    float acc[4][2][4];
    #pragma unroll
    for (int mt = 0; mt < 4; mt++)
        #pragma unroll
        for (int nt = 0; nt < 2; nt++)
            #pragma unroll
            for (int q = 0; q < 4; q++) acc[mt][nt][q] = 0.0f;

    const int NK = K / BK;
    stage(0, sb); cp_commit();

    for (int i = 0; i < NK; i++) {
        const uint32_t stg = sb + (uint32_t)(i & 1) * STAGE_BYTES;
        if (i + 1 < NK) {
            stage(i + 1, sb + (uint32_t)((i + 1) & 1) * STAGE_BYTES);
            cp_commit();
            cp_wait<1>();
        } else {
            cp_wait<0>();
        }
        __syncthreads();

        #pragma unroll
        for (int ks = 0; ks < 2; ks++) {
            const uint32_t kx = (uint32_t)(ks << 5);
            uint32_t bhx[4], blx[4];
            ldsm4(bhx, stg + (bO ^ kx));
            ldsm4(blx, stg + B_PLANE + (bO ^ kx));
            uint32_t bh0[2] = { bhx[0], bhx[2] }, bh1[2] = { bhx[1], bhx[3] };
            uint32_t bl0[2] = { blx[0], blx[2] }, bl1[2] = { blx[1], blx[3] };
            #pragma unroll
            for (int mt = 0; mt < 4; mt++) {
                uint32_t ah[4], al[4];
                const uint32_t am = (aO + mt * 1024) ^ kx;
                ldsm4(ah, stg + am);
                ldsm4(al, stg + A_PLANE + am);
                mma_bf16(acc[mt][0], ah, bh0);
                mma_bf16(acc[mt][1], ah, bh1);
                mma_bf16(acc[mt][0], ah, bl0);
                mma_bf16(acc[mt][1], ah, bl1);
                mma_bf16(acc[mt][0], al, bh0);
                mma_bf16(acc[mt][1], al, bh1);
            }
        }
        __syncthreads();   // protect buf (i+1)&1's... successor stage((i+2)) target = buf i&1
    }

    #pragma unroll
    for (int mt = 0; mt < 4; mt++) {
        #pragma unroll
        for (int h = 0; h < 2; h++) {
            const int row = m0 + wm * 64 + mt * 16 + g + h * 8;
            const size_t base = (size_t)row * ldo;
            #pragma unroll
            for (int nt = 0; nt < 2; nt++) {
                const int col = n0 + wn * 16 + nt * 8 + tig * 2;
                const float d0 = acc[mt][nt][h * 2 + 0];
                const float d1 = acc[mt][nt][h * 2 + 1];
                if (STEP) {
                    float2 ib = *reinterpret_cast<const float2*>(aux0 + base + col);
                    float2 hf = *reinterpret_cast<const float2*>(aux1 + base + col);
                    const float dc0 = colv[col - n0];
                    const float dc1 = colv[col - n0 + 1];
                    const float hn0 = dc0 * hf.x + (1.0f - dc0) * tanh_acc(d0 + ib.x);
                    const float hn1 = dc1 * hf.y + (1.0f - dc1) * tanh_acc(d1 + ib.y);
                    *reinterpret_cast<float2*>(out_full + base + col) = make_float2(hn0, hn1);
                    __nv_bfloat162 hp, lp;
                    split1(hn0, hp.x, lp.x);
                    split1(hn1, hp.y, lp.y);
                    *reinterpret_cast<__nv_bfloat162*>(out_hi + base + col) = hp;
                    *reinterpret_cast<__nv_bfloat162*>(out_lo + base + col) = lp;
                } else {
                    float2 o = make_float2(d0 + colv[col - n0], d1 + colv[col - n0 + 1]);
                    *reinterpret_cast<float2*>(out_full + base + col) = o;
                }
            }
        }
    }
}

extern "C" void kernel_launch(void* const* d_in, const int* in_sizes, int n_in,
                              void* d_out, int out_size) {
    (void)in_sizes; (void)n_in; (void)out_size;
    const float* x   = (const float*)d_in[0];
    const float* h0  = (const float*)d_in[1];
    const float* Wih = (const float*)d_in[2];
    const float* bih = (const float*)d_in[3];
    const float* Whh = (const float*)d_in[4];
    const float* bhh = (const float*)d_in[5];
    const float* tau = (const float*)d_in[6];
    float* out = (float*)d_out;

    float *p_ihb, *p_hfull;
    __nv_bfloat16 *p_hhiA, *p_hloA, *p_hhiB, *p_hloB;
    __nv_bfloat16 *p_xhi, *p_xlo, *p_wihhi, *p_wihlo, *p_whhhi, *p_whhlo;
    cudaGetSymbolAddress((void**)&p_ihb, g_ihb);
    cudaGetSymbolAddress((void**)&p_hfull, g_hfull);
    cudaGetSymbolAddress((void**)&p_hhiA, g_hhiA);
    cudaGetSymbolAddress((void**)&p_hloA, g_hloA);
    cudaGetSymbolAddress((void**)&p_hhiB, g_hhiB);
    cudaGetSymbolAddress((void**)&p_hloB, g_hloB);
    cudaGetSymbolAddress((void**)&p_xhi, g_xhi);
    cudaGetSymbolAddress((void**)&p_xlo, g_xlo);
    cudaGetSymbolAddress((void**)&p_wihhi, g_wihhi);
    cudaGetSymbolAddress((void**)&p_wihlo, g_wihlo);
    cudaGetSymbolAddress((void**)&p_whhhi, g_whhhi);
    cudaGetSymbolAddress((void**)&p_whhlo, g_whhlo);

    cudaFuncSetAttribute(gemm_kernel<false>, cudaFuncAttributeMaxDynamicSharedMemorySize, SMEM_TOTAL);
    cudaFuncSetAttribute(gemm_kernel<true>,  cudaFuncAttributeMaxDynamicSharedMemorySize, SMEM_TOTAL);

    prep_all_kernel<<<512, 256>>>(x, Wih, Whh, h0,
                                  p_xhi, p_xlo, p_wihhi, p_wihlo, p_whhhi, p_whhlo,
                                  p_hfull, p_hhiA, p_hloA);

    dim3 grid(HDIM / BN, BDIM / BM);   // 32 x 32 = 1024 CTAs
    gemm_kernel<false><<<grid, NT, SMEM_TOTAL>>>(p_xhi, p_xlo, p_wihhi, p_wihlo, IDIM,
                                                 bih, bhh, nullptr,
                                                 p_ihb, nullptr, nullptr, HDIM);
    __nv_bfloat16 *hi_in = p_hhiA, *lo_in = p_hloA;
    __nv_bfloat16 *hi_out = p_hhiB, *lo_out = p_hloB;
    for (int s = 0; s < NSTEPS; s++) {
        float* full_dst = (s == NSTEPS - 1) ? out : p_hfull;
        gemm_kernel<true><<<grid, NT, SMEM_TOTAL>>>(hi_in, lo_in, p_whhhi, p_whhlo, HDIM,
                                                    p_ihb, p_hfull, tau,
                                                    full_dst, hi_out, lo_out, HDIM);
        __nv_bfloat16* t;
        t = hi_in; hi_in = hi_out; hi_out = t;
        t = lo_in; lo_in = lo_out; lo_out = t;
    }
}

// round 13
// speedup vs baseline: 1.2916x; 1.2916x over previous
#include <cuda_runtime.h>
#include <cuda_bf16.h>
#include <cuda_fp16.h>
#include <cstdint>

static constexpr int BDIM = 4096;
static constexpr int IDIM = 1024;
static constexpr int HDIM = 2048;
static constexpr int NSTEPS = 10;
static constexpr float DT = 0.1f;

static constexpr int BM = 128, BN = 64, BK = 32;
static constexpr int STAGES = 3;
static constexpr int NT = 256;
// stage: [A16 8K | Abf 8K | Bhi 4K | Blo 4K] = 24 KB
static constexpr int A_PLANE = BM * BK * 2;            // 8 KB
static constexpr int B_PLANE = BN * BK * 2;            // 4 KB
static constexpr int STAGE_BYTES = 2 * A_PLANE + 2 * B_PLANE;   // 24 KB
static constexpr int OFF_BPL = 2 * A_PLANE;            // 16 KB into stage
static constexpr int OFF_COLV = STAGES * STAGE_BYTES;  // 72 KB
static constexpr int SMEM_TOTAL = OFF_COLV + BN * 4 + 16;   // ~72.3 KB -> 3 CTAs/SM

__device__ float g_ihb  [BDIM * HDIM];
__device__ float g_hfull[BDIM * HDIM];
__device__ __half        g_h16A[BDIM * HDIM];
__device__ __nv_bfloat16 g_hbfA[BDIM * HDIM];
__device__ __half        g_h16B[BDIM * HDIM];
__device__ __nv_bfloat16 g_hbfB[BDIM * HDIM];
__device__ __half        g_x16 [BDIM * IDIM];
__device__ __nv_bfloat16 g_xbf [BDIM * IDIM];
__device__ __half        g_wihhi[HDIM * IDIM];
__device__ __nv_bfloat16 g_wihlo[HDIM * IDIM];
__device__ __half        g_whhhi[HDIM * HDIM];
__device__ __nv_bfloat16 g_whhlo[HDIM * HDIM];

__device__ __forceinline__ uint32_t smem_u32(const void* p) {
    uint32_t a;
    asm("{ .reg .u64 t; cvta.to.shared.u64 t, %1; cvt.u32.u64 %0, t; }" : "=r"(a) : "l"(p));
    return a;
}
__device__ __forceinline__ void cp16(uint32_t dst, const void* src) {
    asm volatile("cp.async.cg.shared.global [%0], [%1], 16;" :: "r"(dst), "l"(src) : "memory");
}
__device__ __forceinline__ void cp_commit() { asm volatile("cp.async.commit_group;" ::: "memory"); }
template <int N> __device__ __forceinline__ void cp_wait() {
    asm volatile("cp.async.wait_group %0;" :: "n"(N) : "memory");
}
__device__ __forceinline__ float tanh_acc(float x) {
    float ax = fabsf(x);
    float e = __expf(-2.0f * ax);
    float t = (1.0f - e) / (1.0f + e);
    return copysignf(t, x);
}
__device__ __forceinline__ void mma_f16(float* c, const uint32_t* a, const uint32_t* b) {
    asm volatile(
        "mma.sync.aligned.m16n8k16.row.col.f32.f16.f16.f32 "
        "{%0,%1,%2,%3},{%4,%5,%6,%7},{%8,%9},{%0,%1,%2,%3};"
        : "+f"(c[0]), "+f"(c[1]), "+f"(c[2]), "+f"(c[3])
        : "r"(a[0]), "r"(a[1]), "r"(a[2]), "r"(a[3]), "r"(b[0]), "r"(b[1]));
}
__device__ __forceinline__ void mma_bf16(float* c, const uint32_t* a, const uint32_t* b) {
    asm volatile(
        "mma.sync.aligned.m16n8k16.row.col.f32.bf16.bf16.f32 "
        "{%0,%1,%2,%3},{%4,%5,%6,%7},{%8,%9},{%0,%1,%2,%3};"
        : "+f"(c[0]), "+f"(c[1]), "+f"(c[2]), "+f"(c[3])
        : "r"(a[0]), "r"(a[1]), "r"(a[2]), "r"(a[3]), "r"(b[0]), "r"(b[1]));
}
__device__ __forceinline__ void ldsm4(uint32_t* r, uint32_t addr) {
    asm volatile("ldmatrix.sync.aligned.m8n8.x4.shared.b16 {%0,%1,%2,%3}, [%4];"
                 : "=r"(r[0]), "=r"(r[1]), "=r"(r[2]), "=r"(r[3]) : "r"(addr));
}
// weight: hi = fp16(v), lo = bf16(v - hi)  (bf16 residual: no subnormal hazard)
__device__ __forceinline__ void splitW(float v, __half& hi, __nv_bfloat16& lo) {
    hi = __float2half_rn(v);
    lo = __float2bfloat16(v - __half2float(hi));
}
// activation: both planes are the full value, quantized to each dtype
__device__ __forceinline__ void dualA(float v, __half& h16, __nv_bfloat16& hbf) {
    h16 = __float2half_rn(v);
    hbf = __float2bfloat16(v);
}

// One prep kernel: split x / Wih / Whh, copy+dual-quantize h0.
__global__ void prep_all_kernel(const float* __restrict__ x,
                                const float* __restrict__ Wih,
                                const float* __restrict__ Whh,
                                const float* __restrict__ h0,
                                __half* __restrict__ x16, __nv_bfloat16* __restrict__ xbf,
                                __half* __restrict__ wihhi, __nv_bfloat16* __restrict__ wihlo,
                                __half* __restrict__ whhhi, __nv_bfloat16* __restrict__ whhlo,
                                float* __restrict__ hfull,
                                __half* __restrict__ h16, __nv_bfloat16* __restrict__ hbf) {
    const int stride = gridDim.x * blockDim.x;
    const int t0 = blockIdx.x * blockDim.x + threadIdx.x;
    auto splitW4 = [](float4 v, __half* hi, __nv_bfloat16* lo, int i) {
        __half2 h01, h23; __nv_bfloat162 l01, l23;
        splitW(v.x, h01.x, l01.x); splitW(v.y, h01.y, l01.y);
        splitW(v.z, h23.x, l23.x); splitW(v.w, h23.y, l23.y);
        reinterpret_cast<__half2*>(hi)[i * 2]     = h01;
        reinterpret_cast<__half2*>(hi)[i * 2 + 1] = h23;
        reinterpret_cast<__nv_bfloat162*>(lo)[i * 2]     = l01;
        reinterpret_cast<__nv_bfloat162*>(lo)[i * 2 + 1] = l23;
    };
    auto dualA4 = [](float4 v, __half* h16p, __nv_bfloat16* hbfp, int i) {
        __half2 h01, h23; __nv_bfloat162 b01, b23;
        dualA(v.x, h01.x, b01.x); dualA(v.y, h01.y, b01.y);
        dualA(v.z, h23.x, b23.x); dualA(v.w, h23.y, b23.y);
        reinterpret_cast<__half2*>(h16p)[i * 2]     = h01;
        reinterpret_cast<__half2*>(h16p)[i * 2 + 1] = h23;
        reinterpret_cast<__nv_bfloat162*>(hbfp)[i * 2]     = b01;
        reinterpret_cast<__nv_bfloat162*>(hbfp)[i * 2 + 1] = b23;
    };
    for (int i = t0; i < BDIM * IDIM / 4; i += stride)
        dualA4(reinterpret_cast<const float4*>(x)[i], x16, xbf, i);
    for (int i = t0; i < HDIM * IDIM / 4; i += stride)
        splitW4(reinterpret_cast<const float4*>(Wih)[i], wihhi, wihlo, i);
    for (int i = t0; i < HDIM * HDIM / 4; i += stride)
        splitW4(reinterpret_cast<const float4*>(Whh)[i], whhhi, whhlo, i);
    for (int i = t0; i < BDIM * HDIM / 4; i += stride) {
        float4 v = reinterpret_cast<const float4*>(h0)[i];
        reinterpret_cast<float4*>(hfull)[i] = v;
        dualA4(v, h16, hbf, i);
    }
}

// D[m][n] = sum_k A[m][k]*W[n][k] ; 2-term: A16*Whi (f16) + Abf*Wlo (bf16), fp32 acc.
template <bool STEP>
__global__ __launch_bounds__(NT, 3)
void gemm_kernel(const __half* __restrict__ A16, const __nv_bfloat16* __restrict__ Abf,
                 const __half* __restrict__ Whi, const __nv_bfloat16* __restrict__ Wlo,
                 int K,
                 const float* __restrict__ aux0,   // STEP: ihb      | !STEP: b_ih
                 const float* __restrict__ aux1,   // STEP: hfull_in | !STEP: b_hh
                 const float* __restrict__ tau,
                 float* __restrict__ out_full,
                 __half* __restrict__ out_16, __nv_bfloat16* __restrict__ out_bf,
                 int ldo) {
    extern __shared__ char sm[];
    float* colv = (float*)(sm + OFF_COLV);
    const uint32_t sb = smem_u32(sm);
    const int tid = threadIdx.x;
    const int lane = tid & 31;
    const int wid = tid >> 5;
    const int wm = wid >> 2;      // 0..1
    const int wn = wid & 3;       // 0..3
    const int g = lane >> 2;
    const int tig = lane & 3;
    const int n0 = blockIdx.x * BN;
    const int m0 = blockIdx.y * BM;

    for (int j = tid; j < BN; j += NT)
        colv[j] = STEP ? __expf(-DT / tau[n0 + j]) : (aux0[n0 + j] + aux1[n0 + j]);

    // ldmatrix lane geometry
    const int lrow = ((lane >> 3) & 1) * 8 + (lane & 7);
    const int lkh  = (lane >> 4);

    // staging: 1536 16B-chunks/stage (A:1024, B:512), 6 per thread
    const char* gsrc[6];
    uint32_t sdst[6];
    #pragma unroll
    for (int t = 0; t < 6; t++) {
        int idx = tid + t * NT;
        if (idx < 1024) {
            int p = idx >> 9, rem = idx & 511, r = rem >> 2, j = rem & 3;
            sdst[t] = p * A_PLANE + (uint32_t)(r * 64 + ((j ^ ((r >> 1) & 3)) << 4));
            gsrc[t] = (p ? (const char*)Abf : (const char*)A16)
                      + ((size_t)(m0 + r) * K + j * 8) * 2;
        } else {
            int q = idx - 1024;
            int p = q >> 8, rem = q & 255, r = rem >> 2, j = rem & 3;
            sdst[t] = OFF_BPL + p * B_PLANE + (uint32_t)(r * 64 + ((j ^ ((r >> 1) & 3)) << 4));
            gsrc[t] = (p ? (const char*)Wlo : (const char*)Whi)
                      + ((size_t)(n0 + r) * K + j * 8) * 2;
        }
    }

    const int NK = K / BK;
    auto stage = [&](int i, uint32_t base) {
        const int koff = i * BK * 2;
        #pragma unroll
        for (int t = 0; t < 6; t++) cp16(base + sdst[t], gsrc[t] + koff);
    };

    float acc[4][2][4];
    #pragma unroll
    for (int mt = 0; mt < 4; mt++)
        #pragma unroll
        for (int nt = 0; nt < 2; nt++)
            #pragma unroll
            for (int q = 0; q < 4; q++) acc[mt][nt][q] = 0.0f;

    // per-lane swizzled LDSM offsets
    uint32_t aoff[4][2];   // [mt][ks]
    #pragma unroll
    for (int mt = 0; mt < 4; mt++) {
        const int r = wm * 64 + mt * 16 + lrow;
        const int q = (r >> 1) & 3;
        #pragma unroll
        for (int ks = 0; ks < 2; ks++) {
            const int j = ks * 2 + lkh;
            aoff[mt][ks] = (uint32_t)(r * 64 + ((j ^ q) << 4));
        }
    }
    uint32_t boff[2];      // [ks]
    {
        const int r = wn * 16 + lrow;
        const int q = (r >> 1) & 3;
        #pragma unroll
        for (int ks = 0; ks < 2; ks++) {
            const int j = ks * 2 + lkh;
            boff[ks] = OFF_BPL + (uint32_t)(r * 64 + ((j ^ q) << 4));
        }
    }

    stage(0, sb); cp_commit();
    stage(1, sb + STAGE_BYTES); cp_commit();

    uint32_t buf = 0;   // 0,1,2 rotating
    for (int i = 0; i < NK; i++) {
        if (i < NK - 1) cp_wait<1>(); else cp_wait<0>();
        __syncthreads();
        if (i + 2 < NK) {
            uint32_t nb = buf + 2; if (nb >= 3) nb -= 3;
            stage(i + 2, sb + nb * STAGE_BYTES);
            cp_commit();
        }
        const uint32_t stg = sb + buf * STAGE_BYTES;
        buf++; if (buf == 3) buf = 0;

        #pragma unroll
        for (int ks = 0; ks < 2; ks++) {
            uint32_t bhx[4], blx[4];
            ldsm4(bhx, stg + boff[ks]);                 // Whi (fp16)
            ldsm4(blx, stg + B_PLANE + boff[ks]);       // Wlo (bf16)
            uint32_t bh0[2] = { bhx[0], bhx[2] }, bh1[2] = { bhx[1], bhx[3] };
            uint32_t bl0[2] = { blx[0], blx[2] }, bl1[2] = { blx[1], blx[3] };
            #pragma unroll
            for (int mt = 0; mt < 4; mt++) {
                uint32_t a16[4], abf[4];
                ldsm4(a16, stg + aoff[mt][ks]);             // A fp16 plane
                ldsm4(abf, stg + A_PLANE + aoff[mt][ks]);   // A bf16 plane
                mma_f16 (acc[mt][0], a16, bh0);
                mma_f16 (acc[mt][1], a16, bh1);
                mma_bf16(acc[mt][0], abf, bl0);
                mma_bf16(acc[mt][1], abf, bl1);
            }
        }
    }

    #pragma unroll
    for (int mt = 0; mt < 4; mt++) {
        #pragma unroll
        for (int h = 0; h < 2; h++) {
            const int row = m0 + wm * 64 + mt * 16 + g + h * 8;
            const size_t base = (size_t)row * ldo;
            #pragma unroll
            for (int nt = 0; nt < 2; nt++) {
                const int col = n0 + wn * 16 + nt * 8 + tig * 2;
                const float d0 = acc[mt][nt][h * 2 + 0];
                const float d1 = acc[mt][nt][h * 2 + 1];
                if (STEP) {
                    float2 ib = *reinterpret_cast<const float2*>(aux0 + base + col);
                    float2 hf = *reinterpret_cast<const float2*>(aux1 + base + col);
                    const float dc0 = colv[col - n0];
                    const float dc1 = colv[col - n0 + 1];
                    const float hn0 = dc0 * hf.x + (1.0f - dc0) * tanh_acc(d0 + ib.x);
                    const float hn1 = dc1 * hf.y + (1.0f - dc1) * tanh_acc(d1 + ib.y);
                    *reinterpret_cast<float2*>(out_full + base + col) = make_float2(hn0, hn1);
                    __half2 hp; __nv_bfloat162 bp;
                    dualA(hn0, hp.x, bp.x);
                    dualA(hn1, hp.y, bp.y);
                    *reinterpret_cast<__half2*>(out_16 + base + col) = hp;
                    *reinterpret_cast<__nv_bfloat162*>(out_bf + base + col) = bp;
                } else {
                    float2 o = make_float2(d0 + colv[col - n0], d1 + colv[col - n0 + 1]);
                    *reinterpret_cast<float2*>(out_full + base + col) = o;
                }
            }
        }
    }
}

extern "C" void kernel_launch(void* const* d_in, const int* in_sizes, int n_in,
                              void* d_out, int out_size) {
    (void)in_sizes; (void)n_in; (void)out_size;
    const float* x   = (const float*)d_in[0];
    const float* h0  = (const float*)d_in[1];
    const float* Wih = (const float*)d_in[2];
    const float* bih = (const float*)d_in[3];
    const float* Whh = (const float*)d_in[4];
    const float* bhh = (const float*)d_in[5];
    const float* tau = (const float*)d_in[6];
    float* out = (float*)d_out;

    float *p_ihb, *p_hfull;
    __half *p_h16A, *p_h16B, *p_x16, *p_wihhi, *p_whhhi;
    __nv_bfloat16 *p_hbfA, *p_hbfB, *p_xbf, *p_wihlo, *p_whhlo;
    cudaGetSymbolAddress((void**)&p_ihb, g_ihb);
    cudaGetSymbolAddress((void**)&p_hfull, g_hfull);
    cudaGetSymbolAddress((void**)&p_h16A, g_h16A);
    cudaGetSymbolAddress((void**)&p_hbfA, g_hbfA);
    cudaGetSymbolAddress((void**)&p_h16B, g_h16B);
    cudaGetSymbolAddress((void**)&p_hbfB, g_hbfB);
    cudaGetSymbolAddress((void**)&p_x16, g_x16);
    cudaGetSymbolAddress((void**)&p_xbf, g_xbf);
    cudaGetSymbolAddress((void**)&p_wihhi, g_wihhi);
    cudaGetSymbolAddress((void**)&p_wihlo, g_wihlo);
    cudaGetSymbolAddress((void**)&p_whhhi, g_whhhi);
    cudaGetSymbolAddress((void**)&p_whhlo, g_whhlo);

    cudaFuncSetAttribute(gemm_kernel<false>, cudaFuncAttributeMaxDynamicSharedMemorySize, SMEM_TOTAL);
    cudaFuncSetAttribute(gemm_kernel<true>,  cudaFuncAttributeMaxDynamicSharedMemorySize, SMEM_TOTAL);

    prep_all_kernel<<<512, 256>>>(x, Wih, Whh, h0,
                                  p_x16, p_xbf, p_wihhi, p_wihlo, p_whhhi, p_whhlo,
                                  p_hfull, p_h16A, p_hbfA);

    dim3 grid(HDIM / BN, BDIM / BM);   // 32 x 32 = 1024 CTAs
    gemm_kernel<false><<<grid, NT, SMEM_TOTAL>>>(p_x16, p_xbf, p_wihhi, p_wihlo, IDIM,
                                                 bih, bhh, nullptr,
                                                 p_ihb, nullptr, nullptr, HDIM);
    __half *h16_in = p_h16A, *h16_out = p_h16B;
    __nv_bfloat16 *hbf_in = p_hbfA, *hbf_out = p_hbfB;
    for (int s = 0; s < NSTEPS; s++) {
        float* full_dst = (s == NSTEPS - 1) ? out : p_hfull;
        gemm_kernel<true><<<grid, NT, SMEM_TOTAL>>>(h16_in, hbf_in, p_whhhi, p_whhlo, HDIM,
                                                    p_ihb, p_hfull, tau,
                                                    full_dst, h16_out, hbf_out, HDIM);
        __half* t16 = h16_in; h16_in = h16_out; h16_out = t16;
        __nv_bfloat16* tbf = hbf_in; hbf_in = hbf_out; hbf_out = tbf;
    }
}

// round 14
// speedup vs baseline: 1.3313x; 1.0308x over previous
#include <cuda_runtime.h>
#include <cuda_bf16.h>
#include <cuda_fp16.h>
#include <cstdint>

static constexpr int BDIM = 4096;
static constexpr int IDIM = 1024;
static constexpr int HDIM = 2048;
static constexpr int NSTEPS = 10;
static constexpr float DT = 0.1f;

static constexpr int BM = 128, BN = 64, BK = 32;
static constexpr int STAGES = 3;
static constexpr int NT = 256;
// stage: [A16 8K | Abf 8K | Bhi 4K | Blo 4K] = 24 KB
static constexpr int A_PLANE = BM * BK * 2;            // 8 KB
static constexpr int B_PLANE = BN * BK * 2;            // 4 KB
static constexpr int STAGE_BYTES = 2 * A_PLANE + 2 * B_PLANE;   // 24 KB
static constexpr int OFF_BPL = 2 * A_PLANE;            // 16 KB into stage
static constexpr int OFF_COLV = STAGES * STAGE_BYTES;  // 72 KB
static constexpr int SMEM_TOTAL = OFF_COLV + BN * 4 + 16;   // ~72.3 KB -> 3 CTAs/SM

__device__ float g_ihb  [BDIM * HDIM];
__device__ float g_hfull[BDIM * HDIM];
__device__ __half        g_h16A[BDIM * HDIM];
__device__ __nv_bfloat16 g_hbfA[BDIM * HDIM];
__device__ __half        g_h16B[BDIM * HDIM];
__device__ __nv_bfloat16 g_hbfB[BDIM * HDIM];
__device__ __half        g_x16 [BDIM * IDIM];
__device__ __nv_bfloat16 g_xbf [BDIM * IDIM];
__device__ __half        g_wihhi[HDIM * IDIM];
__device__ __nv_bfloat16 g_wihlo[HDIM * IDIM];
__device__ __half        g_whhhi[HDIM * HDIM];
__device__ __nv_bfloat16 g_whhlo[HDIM * HDIM];

__device__ __forceinline__ uint32_t smem_u32(const void* p) {
    uint32_t a;
    asm("{ .reg .u64 t; cvta.to.shared.u64 t, %1; cvt.u32.u64 %0, t; }" : "=r"(a) : "l"(p));
    return a;
}
__device__ __forceinline__ void cp16(uint32_t dst, const void* src) {
    asm volatile("cp.async.cg.shared.global [%0], [%1], 16;" :: "r"(dst), "l"(src) : "memory");
}
__device__ __forceinline__ void cp_commit() { asm volatile("cp.async.commit_group;" ::: "memory"); }
template <int N> __device__ __forceinline__ void cp_wait() {
    asm volatile("cp.async.wait_group %0;" :: "n"(N) : "memory");
}
__device__ __forceinline__ float tanh_acc(float x) {
    float ax = fabsf(x);
    float e = __expf(-2.0f * ax);
    float t = (1.0f - e) / (1.0f + e);
    return copysignf(t, x);
}
__device__ __forceinline__ void mma_f16(float* c, const uint32_t* a, const uint32_t* b) {
    asm volatile(
        "mma.sync.aligned.m16n8k16.row.col.f32.f16.f16.f32 "
        "{%0,%1,%2,%3},{%4,%5,%6,%7},{%8,%9},{%0,%1,%2,%3};"
        : "+f"(c[0]), "+f"(c[1]), "+f"(c[2]), "+f"(c[3])
        : "r"(a[0]), "r"(a[1]), "r"(a[2]), "r"(a[3]), "r"(b[0]), "r"(b[1]));
}
__device__ __forceinline__ void mma_bf16(float* c, const uint32_t* a, const uint32_t* b) {
    asm volatile(
        "mma.sync.aligned.m16n8k16.row.col.f32.bf16.bf16.f32 "
        "{%0,%1,%2,%3},{%4,%5,%6,%7},{%8,%9},{%0,%1,%2,%3};"
        : "+f"(c[0]), "+f"(c[1]), "+f"(c[2]), "+f"(c[3])
        : "r"(a[0]), "r"(a[1]), "r"(a[2]), "r"(a[3]), "r"(b[0]), "r"(b[1]));
}
__device__ __forceinline__ void ldsm4(uint32_t* r, uint32_t addr) {
    asm volatile("ldmatrix.sync.aligned.m8n8.x4.shared.b16 {%0,%1,%2,%3}, [%4];"
                 : "=r"(r[0]), "=r"(r[1]), "=r"(r[2]), "=r"(r[3]) : "r"(addr));
}
// weight: hi = fp16(v), lo = bf16(v - hi)
__device__ __forceinline__ void splitW(float v, __half& hi, __nv_bfloat16& lo) {
    hi = __float2half_rn(v);
    lo = __float2bfloat16(v - __half2float(hi));
}
// activation: full value quantized to each dtype
__device__ __forceinline__ void dualA(float v, __half& h16, __nv_bfloat16& hbf) {
    h16 = __float2half_rn(v);
    hbf = __float2bfloat16(v);
}

__global__ void prep_all_kernel(const float* __restrict__ x,
                                const float* __restrict__ Wih,
                                const float* __restrict__ Whh,
                                const float* __restrict__ h0,
                                __half* __restrict__ x16, __nv_bfloat16* __restrict__ xbf,
                                __half* __restrict__ wihhi, __nv_bfloat16* __restrict__ wihlo,
                                __half* __restrict__ whhhi, __nv_bfloat16* __restrict__ whhlo,
                                float* __restrict__ hfull,
                                __half* __restrict__ h16, __nv_bfloat16* __restrict__ hbf) {
    const int stride = gridDim.x * blockDim.x;
    const int t0 = blockIdx.x * blockDim.x + threadIdx.x;
    auto splitW4 = [](float4 v, __half* hi, __nv_bfloat16* lo, int i) {
        __half2 h01, h23; __nv_bfloat162 l01, l23;
        splitW(v.x, h01.x, l01.x); splitW(v.y, h01.y, l01.y);
        splitW(v.z, h23.x, l23.x); splitW(v.w, h23.y, l23.y);
        reinterpret_cast<__half2*>(hi)[i * 2]     = h01;
        reinterpret_cast<__half2*>(hi)[i * 2 + 1] = h23;
        reinterpret_cast<__nv_bfloat162*>(lo)[i * 2]     = l01;
        reinterpret_cast<__nv_bfloat162*>(lo)[i * 2 + 1] = l23;
    };
    auto dualA4 = [](float4 v, __half* h16p, __nv_bfloat16* hbfp, int i) {
        __half2 h01, h23; __nv_bfloat162 b01, b23;
        dualA(v.x, h01.x, b01.x); dualA(v.y, h01.y, b01.y);
        dualA(v.z, h23.x, b23.x); dualA(v.w, h23.y, b23.y);
        reinterpret_cast<__half2*>(h16p)[i * 2]     = h01;
        reinterpret_cast<__half2*>(h16p)[i * 2 + 1] = h23;
        reinterpret_cast<__nv_bfloat162*>(hbfp)[i * 2]     = b01;
        reinterpret_cast<__nv_bfloat162*>(hbfp)[i * 2 + 1] = b23;
    };
    for (int i = t0; i < BDIM * IDIM / 4; i += stride)
        dualA4(reinterpret_cast<const float4*>(x)[i], x16, xbf, i);
    for (int i = t0; i < HDIM * IDIM / 4; i += stride)
        splitW4(reinterpret_cast<const float4*>(Wih)[i], wihhi, wihlo, i);
    for (int i = t0; i < HDIM * HDIM / 4; i += stride)
        splitW4(reinterpret_cast<const float4*>(Whh)[i], whhhi, whhlo, i);
    for (int i = t0; i < BDIM * HDIM / 4; i += stride) {
        float4 v = reinterpret_cast<const float4*>(h0)[i];
        reinterpret_cast<float4*>(hfull)[i] = v;
        dualA4(v, h16, hbf, i);
    }
}

// D[m][n] = sum_k A[m][k]*W[n][k] ; 2-term: A16*Whi (f16) + Abf*Wlo (bf16), fp32 acc.
// Warp grid 4x2: warp tile 32 rows x 32 cols.
template <bool STEP>
__global__ __launch_bounds__(NT, 3)
void gemm_kernel(const __half* __restrict__ A16, const __nv_bfloat16* __restrict__ Abf,
                 const __half* __restrict__ Whi, const __nv_bfloat16* __restrict__ Wlo,
                 int K,
                 const float* __restrict__ aux0,   // STEP: ihb      | !STEP: b_ih
                 const float* __restrict__ aux1,   // STEP: hfull_in | !STEP: b_hh
                 const float* __restrict__ tau,
                 float* __restrict__ out_full,
                 __half* __restrict__ out_16, __nv_bfloat16* __restrict__ out_bf,
                 int ldo) {
    extern __shared__ char sm[];
    float* colv = (float*)(sm + OFF_COLV);
    const uint32_t sb = smem_u32(sm);
    const int tid = threadIdx.x;
    const int lane = tid & 31;
    const int wid = tid >> 5;
    const int wm = wid >> 1;      // 0..3 -> 32 rows each
    const int wn = wid & 1;       // 0..1 -> 32 cols each
    const int g = lane >> 2;
    const int tig = lane & 3;
    const int n0 = blockIdx.x * BN;
    const int m0 = blockIdx.y * BM;

    for (int j = tid; j < BN; j += NT)
        colv[j] = STEP ? __expf(-DT / tau[n0 + j]) : (aux0[n0 + j] + aux1[n0 + j]);

    // ldmatrix lane geometry
    const int lrow = ((lane >> 3) & 1) * 8 + (lane & 7);
    const int lkh  = (lane >> 4);

    // staging: 1536 16B-chunks/stage (A:1024, B:512), 6 per thread
    const char* gsrc[6];
    uint32_t sdst[6];
    #pragma unroll
    for (int t = 0; t < 6; t++) {
        int idx = tid + t * NT;
        if (idx < 1024) {
            int p = idx >> 9, rem = idx & 511, r = rem >> 2, j = rem & 3;
            sdst[t] = p * A_PLANE + (uint32_t)(r * 64 + ((j ^ ((r >> 1) & 3)) << 4));
            gsrc[t] = (p ? (const char*)Abf : (const char*)A16)
                      + ((size_t)(m0 + r) * K + j * 8) * 2;
        } else {
            int q = idx - 1024;
            int p = q >> 8, rem = q & 255, r = rem >> 2, j = rem & 3;
            sdst[t] = OFF_BPL + p * B_PLANE + (uint32_t)(r * 64 + ((j ^ ((r >> 1) & 3)) << 4));
            gsrc[t] = (p ? (const char*)Wlo : (const char*)Whi)
                      + ((size_t)(n0 + r) * K + j * 8) * 2;
        }
    }

    const int NK = K / BK;
    auto stage = [&](int i, uint32_t base) {
        const int koff = i * BK * 2;
        #pragma unroll
        for (int t = 0; t < 6; t++) cp16(base + sdst[t], gsrc[t] + koff);
    };

    float acc[2][4][4];
    #pragma unroll
    for (int mt = 0; mt < 2; mt++)
        #pragma unroll
        for (int nt = 0; nt < 4; nt++)
            #pragma unroll
            for (int q = 0; q < 4; q++) acc[mt][nt][q] = 0.0f;

    // per-lane swizzled LDSM offsets
    uint32_t aoff[2][2];   // [mt][ks]: rows wm*32 + mt*16
    #pragma unroll
    for (int mt = 0; mt < 2; mt++) {
        const int r = wm * 32 + mt * 16 + lrow;
        const int q = (r >> 1) & 3;
        #pragma unroll
        for (int ks = 0; ks < 2; ks++) {
            const int j = ks * 2 + lkh;
            aoff[mt][ks] = (uint32_t)(r * 64 + ((j ^ q) << 4));
        }
    }
    uint32_t boff[2][2];   // [nh][ks]: rows wn*32 + nh*16
    #pragma unroll
    for (int nh = 0; nh < 2; nh++) {
        const int r = wn * 32 + nh * 16 + lrow;
        const int q = (r >> 1) & 3;
        #pragma unroll
        for (int ks = 0; ks < 2; ks++) {
            const int j = ks * 2 + lkh;
            boff[nh][ks] = OFF_BPL + (uint32_t)(r * 64 + ((j ^ q) << 4));
        }
    }

    stage(0, sb); cp_commit();
    stage(1, sb + STAGE_BYTES); cp_commit();

    uint32_t buf = 0;   // 0,1,2 rotating
    for (int i = 0; i < NK; i++) {
        if (i < NK - 1) cp_wait<1>(); else cp_wait<0>();
        __syncthreads();
        if (i + 2 < NK) {
            uint32_t nb = buf + 2; if (nb >= 3) nb -= 3;
            stage(i + 2, sb + nb * STAGE_BYTES);
            cp_commit();
        }
        const uint32_t stg = sb + buf * STAGE_BYTES;
        buf++; if (buf == 3) buf = 0;

        #pragma unroll
        for (int ks = 0; ks < 2; ks++) {
            uint32_t bhx[4], bhy[4], blx[4], bly[4];
            ldsm4(bhx, stg + boff[0][ks]);                 // Whi n 0-15
            ldsm4(bhy, stg + boff[1][ks]);                 // Whi n 16-31
            ldsm4(blx, stg + B_PLANE + boff[0][ks]);       // Wlo n 0-15
            ldsm4(bly, stg + B_PLANE + boff[1][ks]);       // Wlo n 16-31
            uint32_t bh0[2] = { bhx[0], bhx[2] }, bh1[2] = { bhx[1], bhx[3] };
            uint32_t bh2[2] = { bhy[0], bhy[2] }, bh3[2] = { bhy[1], bhy[3] };
            uint32_t bl0[2] = { blx[0], blx[2] }, bl1[2] = { blx[1], blx[3] };
            uint32_t bl2[2] = { bly[0], bly[2] }, bl3[2] = { bly[1], bly[3] };
            #pragma unroll
            for (int mt = 0; mt < 2; mt++) {
                uint32_t a16[4], abf[4];
                ldsm4(a16, stg + aoff[mt][ks]);             // A fp16 plane
                ldsm4(abf, stg + A_PLANE + aoff[mt][ks]);   // A bf16 plane
                mma_f16 (acc[mt][0], a16, bh0);
                mma_f16 (acc[mt][1], a16, bh1);
                mma_f16 (acc[mt][2], a16, bh2);
                mma_f16 (acc[mt][3], a16, bh3);
                mma_bf16(acc[mt][0], abf, bl0);
                mma_bf16(acc[mt][1], abf, bl1);
                mma_bf16(acc[mt][2], abf, bl2);
                mma_bf16(acc[mt][3], abf, bl3);
            }
        }
    }

    #pragma unroll
    for (int mt = 0; mt < 2; mt++) {
        #pragma unroll
        for (int h = 0; h < 2; h++) {
            const int row = m0 + wm * 32 + mt * 16 + g + h * 8;
            const size_t base = (size_t)row * ldo;
            #pragma unroll
            for (int nt = 0; nt < 4; nt++) {
                const int col = n0 + wn * 32 + nt * 8 + tig * 2;
                const float d0 = acc[mt][nt][h * 2 + 0];
                const float d1 = acc[mt][nt][h * 2 + 1];
                if (STEP) {
                    float2 ib = *reinterpret_cast<const float2*>(aux0 + base + col);
                    float2 hf = *reinterpret_cast<const float2*>(aux1 + base + col);
                    const float dc0 = colv[col - n0];
                    const float dc1 = colv[col - n0 + 1];
                    const float hn0 = dc0 * hf.x + (1.0f - dc0) * tanh_acc(d0 + ib.x);
                    const float hn1 = dc1 * hf.y + (1.0f - dc1) * tanh_acc(d1 + ib.y);
                    *reinterpret_cast<float2*>(out_full + base + col) = make_float2(hn0, hn1);
                    __half2 hp; __nv_bfloat162 bp;
                    dualA(hn0, hp.x, bp.x);
                    dualA(hn1, hp.y, bp.y);
                    *reinterpret_cast<__half2*>(out_16 + base + col) = hp;
                    *reinterpret_cast<__nv_bfloat162*>(out_bf + base + col) = bp;
                } else {
                    float2 o = make_float2(d0 + colv[col - n0], d1 + colv[col - n0 + 1]);
                    *reinterpret_cast<float2*>(out_full + base + col) = o;
                }
            }
        }
    }
}

extern "C" void kernel_launch(void* const* d_in, const int* in_sizes, int n_in,
                              void* d_out, int out_size) {
    (void)in_sizes; (void)n_in; (void)out_size;
    const float* x   = (const float*)d_in[0];
    const float* h0  = (const float*)d_in[1];
    const float* Wih = (const float*)d_in[2];
    const float* bih = (const float*)d_in[3];
    const float* Whh = (const float*)d_in[4];
    const float* bhh = (const float*)d_in[5];
    const float* tau = (const float*)d_in[6];
    float* out = (float*)d_out;

    float *p_ihb, *p_hfull;
    __half *p_h16A, *p_h16B, *p_x16, *p_wihhi, *p_whhhi;
    __nv_bfloat16 *p_hbfA, *p_hbfB, *p_xbf, *p_wihlo, *p_whhlo;
    cudaGetSymbolAddress((void**)&p_ihb, g_ihb);
    cudaGetSymbolAddress((void**)&p_hfull, g_hfull);
    cudaGetSymbolAddress((void**)&p_h16A, g_h16A);
    cudaGetSymbolAddress((void**)&p_hbfA, g_hbfA);
    cudaGetSymbolAddress((void**)&p_h16B, g_h16B);
    cudaGetSymbolAddress((void**)&p_hbfB, g_hbfB);
    cudaGetSymbolAddress((void**)&p_x16, g_x16);
    cudaGetSymbolAddress((void**)&p_xbf, g_xbf);
    cudaGetSymbolAddress((void**)&p_wihhi, g_wihhi);
    cudaGetSymbolAddress((void**)&p_wihlo, g_wihlo);
    cudaGetSymbolAddress((void**)&p_whhhi, g_whhhi);
    cudaGetSymbolAddress((void**)&p_whhlo, g_whhlo);

    cudaFuncSetAttribute(gemm_kernel<false>, cudaFuncAttributeMaxDynamicSharedMemorySize, SMEM_TOTAL);
    cudaFuncSetAttribute(gemm_kernel<true>,  cudaFuncAttributeMaxDynamicSharedMemorySize, SMEM_TOTAL);

    prep_all_kernel<<<512, 256>>>(x, Wih, Whh, h0,
                                  p_x16, p_xbf, p_wihhi, p_wihlo, p_whhhi, p_whhlo,
                                  p_hfull, p_h16A, p_hbfA);

    dim3 grid(HDIM / BN, BDIM / BM);   // 32 x 32 = 1024 CTAs
    gemm_kernel<false><<<grid, NT, SMEM_TOTAL>>>(p_x16, p_xbf, p_wihhi, p_wihlo, IDIM,
                                                 bih, bhh, nullptr,
                                                 p_ihb, nullptr, nullptr, HDIM);
    __half *h16_in = p_h16A, *h16_out = p_h16B;
    __nv_bfloat16 *hbf_in = p_hbfA, *hbf_out = p_hbfB;
    for (int s = 0; s < NSTEPS; s++) {
        float* full_dst = (s == NSTEPS - 1) ? out : p_hfull;
        gemm_kernel<true><<<grid, NT, SMEM_TOTAL>>>(h16_in, hbf_in, p_whhhi, p_whhlo, HDIM,
                                                    p_ihb, p_hfull, tau,
                                                    full_dst, h16_out, hbf_out, HDIM);
        __half* t16 = h16_in; h16_in = h16_out; h16_out = t16;
        __nv_bfloat16* tbf = hbf_in; hbf_in = hbf_out; hbf_out = tbf;
    }
}

// round 15
// speedup vs baseline: 2.2519x; 1.6915x over previous
#include <cuda_runtime.h>
#include <cuda_bf16.h>
#include <cuda_fp16.h>
#include <cstdint>

static constexpr int BDIM = 4096;
static constexpr int IDIM = 1024;
static constexpr int HDIM = 2048;
static constexpr int NSTEPS = 10;
static constexpr float DT = 0.1f;

static constexpr int BM = 128, BN = 64, BK = 32;
static constexpr int NT = 256;

// ---- ih kernel (2-term): stage [A16 8K | Abf 8K | Bhi 4K | Blo 4K] = 24 KB, 3 stages
static constexpr int A_PLANE = BM * BK * 2;            // 8 KB
static constexpr int B_PLANE = BN * BK * 2;            // 4 KB
static constexpr int STAGE_BYTES = 2 * A_PLANE + 2 * B_PLANE;   // 24 KB
static constexpr int OFF_BPL = 2 * A_PLANE;            // 16 KB
static constexpr int OFF_COLV = 3 * STAGE_BYTES;       // 72 KB
static constexpr int SMEM_TOTAL = OFF_COLV + BN * 4 + 16;

// ---- step kernel (1-term fp16): stage [A16 8K | B16 4K] = 12 KB, 3 stages
static constexpr int S_STAGE = A_PLANE + B_PLANE;      // 12 KB
static constexpr int S_OFF_B = A_PLANE;                // 8 KB
static constexpr int S_OFF_COLV = 3 * S_STAGE;         // 36 KB
static constexpr int S_SMEM_TOTAL = S_OFF_COLV + BN * 4 + 16;   // ~36.3 KB -> occ 4

__device__ float g_ihb  [BDIM * HDIM];
__device__ float g_hfull[BDIM * HDIM];
__device__ __half        g_h16A[BDIM * HDIM];
__device__ __half        g_h16B[BDIM * HDIM];
__device__ __half        g_x16 [BDIM * IDIM];
__device__ __nv_bfloat16 g_xbf [BDIM * IDIM];
__device__ __half        g_wihhi[HDIM * IDIM];
__device__ __nv_bfloat16 g_wihlo[HDIM * IDIM];
__device__ __half        g_whhhi[HDIM * HDIM];

__device__ __forceinline__ uint32_t smem_u32(const void* p) {
    uint32_t a;
    asm("{ .reg .u64 t; cvta.to.shared.u64 t, %1; cvt.u32.u64 %0, t; }" : "=r"(a) : "l"(p));
    return a;
}
__device__ __forceinline__ void cp16(uint32_t dst, const void* src) {
    asm volatile("cp.async.cg.shared.global [%0], [%1], 16;" :: "r"(dst), "l"(src) : "memory");
}
__device__ __forceinline__ void cp_commit() { asm volatile("cp.async.commit_group;" ::: "memory"); }
template <int N> __device__ __forceinline__ void cp_wait() {
    asm volatile("cp.async.wait_group %0;" :: "n"(N) : "memory");
}
__device__ __forceinline__ float tanh_acc(float x) {
    float ax = fabsf(x);
    float e = __expf(-2.0f * ax);
    float t = (1.0f - e) / (1.0f + e);
    return copysignf(t, x);
}
__device__ __forceinline__ void mma_f16(float* c, const uint32_t* a, const uint32_t* b) {
    asm volatile(
        "mma.sync.aligned.m16n8k16.row.col.f32.f16.f16.f32 "
        "{%0,%1,%2,%3},{%4,%5,%6,%7},{%8,%9},{%0,%1,%2,%3};"
        : "+f"(c[0]), "+f"(c[1]), "+f"(c[2]), "+f"(c[3])
        : "r"(a[0]), "r"(a[1]), "r"(a[2]), "r"(a[3]), "r"(b[0]), "r"(b[1]));
}
__device__ __forceinline__ void mma_bf16(float* c, const uint32_t* a, const uint32_t* b) {
    asm volatile(
        "mma.sync.aligned.m16n8k16.row.col.f32.bf16.bf16.f32 "
        "{%0,%1,%2,%3},{%4,%5,%6,%7},{%8,%9},{%0,%1,%2,%3};"
        : "+f"(c[0]), "+f"(c[1]), "+f"(c[2]), "+f"(c[3])
        : "r"(a[0]), "r"(a[1]), "r"(a[2]), "r"(a[3]), "r"(b[0]), "r"(b[1]));
}
__device__ __forceinline__ void ldsm4(uint32_t* r, uint32_t addr) {
    asm volatile("ldmatrix.sync.aligned.m8n8.x4.shared.b16 {%0,%1,%2,%3}, [%4];"
                 : "=r"(r[0]), "=r"(r[1]), "=r"(r[2]), "=r"(r[3]) : "r"(addr));
}
__device__ __forceinline__ void splitW(float v, __half& hi, __nv_bfloat16& lo) {
    hi = __float2half_rn(v);
    lo = __float2bfloat16(v - __half2float(hi));
}

__global__ void prep_all_kernel(const float* __restrict__ x,
                                const float* __restrict__ Wih,
                                const float* __restrict__ Whh,
                                const float* __restrict__ h0,
                                __half* __restrict__ x16, __nv_bfloat16* __restrict__ xbf,
                                __half* __restrict__ wihhi, __nv_bfloat16* __restrict__ wihlo,
                                __half* __restrict__ whhhi,
                                float* __restrict__ hfull, __half* __restrict__ h16) {
    const int stride = gridDim.x * blockDim.x;
    const int t0 = blockIdx.x * blockDim.x + threadIdx.x;
    for (int i = t0; i < BDIM * IDIM / 4; i += stride) {
        float4 v = reinterpret_cast<const float4*>(x)[i];
        __half2 h01, h23; __nv_bfloat162 b01, b23;
        h01.x = __float2half_rn(v.x); b01.x = __float2bfloat16(v.x);
        h01.y = __float2half_rn(v.y); b01.y = __float2bfloat16(v.y);
        h23.x = __float2half_rn(v.z); b23.x = __float2bfloat16(v.z);
        h23.y = __float2half_rn(v.w); b23.y = __float2bfloat16(v.w);
        reinterpret_cast<__half2*>(x16)[i * 2]     = h01;
        reinterpret_cast<__half2*>(x16)[i * 2 + 1] = h23;
        reinterpret_cast<__nv_bfloat162*>(xbf)[i * 2]     = b01;
        reinterpret_cast<__nv_bfloat162*>(xbf)[i * 2 + 1] = b23;
    }
    for (int i = t0; i < HDIM * IDIM / 4; i += stride) {
        float4 v = reinterpret_cast<const float4*>(Wih)[i];
        __half2 h01, h23; __nv_bfloat162 l01, l23;
        splitW(v.x, h01.x, l01.x); splitW(v.y, h01.y, l01.y);
        splitW(v.z, h23.x, l23.x); splitW(v.w, h23.y, l23.y);
        reinterpret_cast<__half2*>(wihhi)[i * 2]     = h01;
        reinterpret_cast<__half2*>(wihhi)[i * 2 + 1] = h23;
        reinterpret_cast<__nv_bfloat162*>(wihlo)[i * 2]     = l01;
        reinterpret_cast<__nv_bfloat162*>(wihlo)[i * 2 + 1] = l23;
    }
    for (int i = t0; i < HDIM * HDIM / 4; i += stride) {
        float4 v = reinterpret_cast<const float4*>(Whh)[i];
        __half2 h01, h23;
        h01.x = __float2half_rn(v.x); h01.y = __float2half_rn(v.y);
        h23.x = __float2half_rn(v.z); h23.y = __float2half_rn(v.w);
        reinterpret_cast<__half2*>(whhhi)[i * 2]     = h01;
        reinterpret_cast<__half2*>(whhhi)[i * 2 + 1] = h23;
    }
    for (int i = t0; i < BDIM * HDIM / 4; i += stride) {
        float4 v = reinterpret_cast<const float4*>(h0)[i];
        reinterpret_cast<float4*>(hfull)[i] = v;
        __half2 h01, h23;
        h01.x = __float2half_rn(v.x); h01.y = __float2half_rn(v.y);
        h23.x = __float2half_rn(v.z); h23.y = __float2half_rn(v.w);
        reinterpret_cast<__half2*>(h16)[i * 2]     = h01;
        reinterpret_cast<__half2*>(h16)[i * 2 + 1] = h23;
    }
}

// ---------------- ih GEMM: 2-term (A16*Whi f16 + Abf*Wlo bf16), warp grid 4x2 ----
__global__ __launch_bounds__(NT, 3)
void ih_kernel(const __half* __restrict__ A16, const __nv_bfloat16* __restrict__ Abf,
               const __half* __restrict__ Whi, const __nv_bfloat16* __restrict__ Wlo,
               int K,
               const float* __restrict__ bih, const float* __restrict__ bhh,
               float* __restrict__ out_full, int ldo) {
    extern __shared__ char sm[];
    float* colv = (float*)(sm + OFF_COLV);
    const uint32_t sb = smem_u32(sm);
    const int tid = threadIdx.x;
    const int lane = tid & 31;
    const int wid = tid >> 5;
    const int wm = wid >> 1, wn = wid & 1;
    const int g = lane >> 2, tig = lane & 3;
    const int n0 = blockIdx.x * BN;
    const int m0 = blockIdx.y * BM;

    for (int j = tid; j < BN; j += NT) colv[j] = bih[n0 + j] + bhh[n0 + j];

    const int lrow = ((lane >> 3) & 1) * 8 + (lane & 7);
    const int lkh  = (lane >> 4);

    const char* gsrc[6];
    uint32_t sdst[6];
    #pragma unroll
    for (int t = 0; t < 6; t++) {
        int idx = tid + t * NT;
        if (idx < 1024) {
            int p = idx >> 9, rem = idx & 511, r = rem >> 2, j = rem & 3;
            sdst[t] = p * A_PLANE + (uint32_t)(r * 64 + ((j ^ ((r >> 1) & 3)) << 4));
            gsrc[t] = (p ? (const char*)Abf : (const char*)A16)
                      + ((size_t)(m0 + r) * K + j * 8) * 2;
        } else {
            int q = idx - 1024;
            int p = q >> 8, rem = q & 255, r = rem >> 2, j = rem & 3;
            sdst[t] = OFF_BPL + p * B_PLANE + (uint32_t)(r * 64 + ((j ^ ((r >> 1) & 3)) << 4));
            gsrc[t] = (p ? (const char*)Wlo : (const char*)Whi)
                      + ((size_t)(n0 + r) * K + j * 8) * 2;
        }
    }
    const int NK = K / BK;
    auto stage = [&](int i, uint32_t base) {
        const int koff = i * BK * 2;
        #pragma unroll
        for (int t = 0; t < 6; t++) cp16(base + sdst[t], gsrc[t] + koff);
    };

    float acc[2][4][4];
    #pragma unroll
    for (int mt = 0; mt < 2; mt++)
        #pragma unroll
        for (int nt = 0; nt < 4; nt++)
            #pragma unroll
            for (int q = 0; q < 4; q++) acc[mt][nt][q] = 0.0f;

    uint32_t aoff[2][2], boff[2][2];
    #pragma unroll
    for (int mt = 0; mt < 2; mt++) {
        const int r = wm * 32 + mt * 16 + lrow;
        const int q = (r >> 1) & 3;
        #pragma unroll
        for (int ks = 0; ks < 2; ks++)
            aoff[mt][ks] = (uint32_t)(r * 64 + (((ks * 2 + lkh) ^ q) << 4));
    }
    #pragma unroll
    for (int nh = 0; nh < 2; nh++) {
        const int r = wn * 32 + nh * 16 + lrow;
        const int q = (r >> 1) & 3;
        #pragma unroll
        for (int ks = 0; ks < 2; ks++)
            boff[nh][ks] = OFF_BPL + (uint32_t)(r * 64 + (((ks * 2 + lkh) ^ q) << 4));
    }

    stage(0, sb); cp_commit();
    stage(1, sb + STAGE_BYTES); cp_commit();
    uint32_t buf = 0;
    for (int i = 0; i < NK; i++) {
        if (i < NK - 1) cp_wait<1>(); else cp_wait<0>();
        __syncthreads();
        if (i + 2 < NK) {
            uint32_t nb = buf + 2; if (nb >= 3) nb -= 3;
            stage(i + 2, sb + nb * STAGE_BYTES);
            cp_commit();
        }
        const uint32_t stg = sb + buf * STAGE_BYTES;
        buf++; if (buf == 3) buf = 0;
        #pragma unroll
        for (int ks = 0; ks < 2; ks++) {
            uint32_t bhx[4], bhy[4], blx[4], bly[4];
            ldsm4(bhx, stg + boff[0][ks]);
            ldsm4(bhy, stg + boff[1][ks]);
            ldsm4(blx, stg + B_PLANE + boff[0][ks]);
            ldsm4(bly, stg + B_PLANE + boff[1][ks]);
            uint32_t bh0[2] = { bhx[0], bhx[2] }, bh1[2] = { bhx[1], bhx[3] };
            uint32_t bh2[2] = { bhy[0], bhy[2] }, bh3[2] = { bhy[1], bhy[3] };
            uint32_t bl0[2] = { blx[0], blx[2] }, bl1[2] = { blx[1], blx[3] };
            uint32_t bl2[2] = { bly[0], bly[2] }, bl3[2] = { bly[1], bly[3] };
            #pragma unroll
            for (int mt = 0; mt < 2; mt++) {
                uint32_t a16[4], abf[4];
                ldsm4(a16, stg + aoff[mt][ks]);
                ldsm4(abf, stg + A_PLANE + aoff[mt][ks]);
                mma_f16 (acc[mt][0], a16, bh0);
                mma_f16 (acc[mt][1], a16, bh1);
                mma_f16 (acc[mt][2], a16, bh2);
                mma_f16 (acc[mt][3], a16, bh3);
                mma_bf16(acc[mt][0], abf, bl0);
                mma_bf16(acc[mt][1], abf, bl1);
                mma_bf16(acc[mt][2], abf, bl2);
                mma_bf16(acc[mt][3], abf, bl3);
            }
        }
    }
    #pragma unroll
    for (int mt = 0; mt < 2; mt++)
        #pragma unroll
        for (int h = 0; h < 2; h++) {
            const int row = m0 + wm * 32 + mt * 16 + g + h * 8;
            const size_t base = (size_t)row * ldo;
            #pragma unroll
            for (int nt = 0; nt < 4; nt++) {
                const int col = n0 + wn * 32 + nt * 8 + tig * 2;
                float2 o = make_float2(acc[mt][nt][h * 2] + colv[col - n0],
                                       acc[mt][nt][h * 2 + 1] + colv[col - n0 + 1]);
                *reinterpret_cast<float2*>(out_full + base + col) = o;
            }
        }
}

// ---------------- step GEMM: 1-term fp16 (A16*W16), warp grid 4x2, occ 4 ----------
__global__ __launch_bounds__(NT, 4)
void step_kernel(const __half* __restrict__ A16, const __half* __restrict__ W16,
                 const float* __restrict__ ihb, const float* __restrict__ hfull,
                 const float* __restrict__ tau,
                 float* __restrict__ out_full, __half* __restrict__ out_16, int ldo) {
    extern __shared__ char sm[];
    float* colv = (float*)(sm + S_OFF_COLV);
    const uint32_t sb = smem_u32(sm);
    const int K = HDIM;
    const int tid = threadIdx.x;
    const int lane = tid & 31;
    const int wid = tid >> 5;
    const int wm = wid >> 1, wn = wid & 1;
    const int g = lane >> 2, tig = lane & 3;
    const int n0 = blockIdx.x * BN;
    const int m0 = blockIdx.y * BM;

    for (int j = tid; j < BN; j += NT) colv[j] = __expf(-DT / tau[n0 + j]);

    const int lrow = ((lane >> 3) & 1) * 8 + (lane & 7);
    const int lkh  = (lane >> 4);

    // staging: 768 chunks/stage (A:512, B:256), 3 per thread
    const char* gsrc[3];
    uint32_t sdst[3];
    #pragma unroll
    for (int t = 0; t < 3; t++) {
        int idx = tid + t * NT;
        if (idx < 512) {
            int r = idx >> 2, j = idx & 3;
            sdst[t] = (uint32_t)(r * 64 + ((j ^ ((r >> 1) & 3)) << 4));
            gsrc[t] = (const char*)A16 + ((size_t)(m0 + r) * K + j * 8) * 2;
        } else {
            int q = idx - 512;
            int r = q >> 2, j = q & 3;
            sdst[t] = S_OFF_B + (uint32_t)(r * 64 + ((j ^ ((r >> 1) & 3)) << 4));
            gsrc[t] = (const char*)W16 + ((size_t)(n0 + r) * K + j * 8) * 2;
        }
    }
    const int NK = K / BK;
    auto stage = [&](int i, uint32_t base) {
        const int koff = i * BK * 2;
        #pragma unroll
        for (int t = 0; t < 3; t++) cp16(base + sdst[t], gsrc[t] + koff);
    };

    float acc[2][4][4];
    #pragma unroll
    for (int mt = 0; mt < 2; mt++)
        #pragma unroll
        for (int nt = 0; nt < 4; nt++)
            #pragma unroll
            for (int q = 0; q < 4; q++) acc[mt][nt][q] = 0.0f;

    uint32_t aoff[2][2], boff[2][2];
    #pragma unroll
    for (int mt = 0; mt < 2; mt++) {
        const int r = wm * 32 + mt * 16 + lrow;
        const int q = (r >> 1) & 3;
        #pragma unroll
        for (int ks = 0; ks < 2; ks++)
            aoff[mt][ks] = (uint32_t)(r * 64 + (((ks * 2 + lkh) ^ q) << 4));
    }
    #pragma unroll
    for (int nh = 0; nh < 2; nh++) {
        const int r = wn * 32 + nh * 16 + lrow;
        const int q = (r >> 1) & 3;
        #pragma unroll
        for (int ks = 0; ks < 2; ks++)
            boff[nh][ks] = S_OFF_B + (uint32_t)(r * 64 + (((ks * 2 + lkh) ^ q) << 4));
    }

    stage(0, sb); cp_commit();
    stage(1, sb + S_STAGE); cp_commit();
    uint32_t buf = 0;
    for (int i = 0; i < NK; i++) {
        if (i < NK - 1) cp_wait<1>(); else cp_wait<0>();
        __syncthreads();
        if (i + 2 < NK) {
            uint32_t nb = buf + 2; if (nb >= 3) nb -= 3;
            stage(i + 2, sb + nb * S_STAGE);
            cp_commit();
        }
        const uint32_t stg = sb + buf * S_STAGE;
        buf++; if (buf == 3) buf = 0;
        #pragma unroll
        for (int ks = 0; ks < 2; ks++) {
            uint32_t bhx[4], bhy[4];
            ldsm4(bhx, stg + boff[0][ks]);
            ldsm4(bhy, stg + boff[1][ks]);
            uint32_t b0[2] = { bhx[0], bhx[2] }, b1[2] = { bhx[1], bhx[3] };
            uint32_t b2[2] = { bhy[0], bhy[2] }, b3[2] = { bhy[1], bhy[3] };
            #pragma unroll
            for (int mt = 0; mt < 2; mt++) {
                uint32_t a16[4];
                ldsm4(a16, stg + aoff[mt][ks]);
                mma_f16(acc[mt][0], a16, b0);
                mma_f16(acc[mt][1], a16, b1);
                mma_f16(acc[mt][2], a16, b2);
                mma_f16(acc[mt][3], a16, b3);
            }
        }
    }

    #pragma unroll
    for (int mt = 0; mt < 2; mt++)
        #pragma unroll
        for (int h = 0; h < 2; h++) {
            const int row = m0 + wm * 32 + mt * 16 + g + h * 8;
            const size_t base = (size_t)row * ldo;
            #pragma unroll
            for (int nt = 0; nt < 4; nt++) {
                const int col = n0 + wn * 32 + nt * 8 + tig * 2;
                float2 ib = *reinterpret_cast<const float2*>(ihb + base + col);
                float2 hf = *reinterpret_cast<const float2*>(hfull + base + col);
                const float dc0 = colv[col - n0];
                const float dc1 = colv[col - n0 + 1];
                const float hn0 = dc0 * hf.x + (1.0f - dc0) * tanh_acc(acc[mt][nt][h*2]   + ib.x);
                const float hn1 = dc1 * hf.y + (1.0f - dc1) * tanh_acc(acc[mt][nt][h*2+1] + ib.y);
                *reinterpret_cast<float2*>(out_full + base + col) = make_float2(hn0, hn1);
                __half2 hp;
                hp.x = __float2half_rn(hn0);
                hp.y = __float2half_rn(hn1);
                *reinterpret_cast<__half2*>(out_16 + base + col) = hp;
            }
        }
}

extern "C" void kernel_launch(void* const* d_in, const int* in_sizes, int n_in,
                              void* d_out, int out_size) {
    (void)in_sizes; (void)n_in; (void)out_size;
    const float* x   = (const float*)d_in[0];
    const float* h0  = (const float*)d_in[1];
    const float* Wih = (const float*)d_in[2];
    const float* bih = (const float*)d_in[3];
    const float* Whh = (const float*)d_in[4];
    const float* bhh = (const float*)d_in[5];
    const float* tau = (const float*)d_in[6];
    float* out = (float*)d_out;

    float *p_ihb, *p_hfull;
    __half *p_h16A, *p_h16B, *p_x16, *p_wihhi, *p_whhhi;
    __nv_bfloat16 *p_xbf, *p_wihlo;
    cudaGetSymbolAddress((void**)&p_ihb, g_ihb);
    cudaGetSymbolAddress((void**)&p_hfull, g_hfull);
    cudaGetSymbolAddress((void**)&p_h16A, g_h16A);
    cudaGetSymbolAddress((void**)&p_h16B, g_h16B);
    cudaGetSymbolAddress((void**)&p_x16, g_x16);
    cudaGetSymbolAddress((void**)&p_xbf, g_xbf);
    cudaGetSymbolAddress((void**)&p_wihhi, g_wihhi);
    cudaGetSymbolAddress((void**)&p_wihlo, g_wihlo);
    cudaGetSymbolAddress((void**)&p_whhhi, g_whhhi);

    cudaFuncSetAttribute(ih_kernel,  cudaFuncAttributeMaxDynamicSharedMemorySize, SMEM_TOTAL);
    cudaFuncSetAttribute(step_kernel, cudaFuncAttributeMaxDynamicSharedMemorySize, S_SMEM_TOTAL);

    prep_all_kernel<<<512, 256>>>(x, Wih, Whh, h0,
                                  p_x16, p_xbf, p_wihhi, p_wihlo, p_whhhi,
                                  p_hfull, p_h16A);

    dim3 grid(HDIM / BN, BDIM / BM);   // 32 x 32 = 1024 CTAs
    ih_kernel<<<grid, NT, SMEM_TOTAL>>>(p_x16, p_xbf, p_wihhi, p_wihlo, IDIM,
                                        bih, bhh, p_ihb, HDIM);
    __half *h16_in = p_h16A, *h16_out = p_h16B;
    for (int s = 0; s < NSTEPS; s++) {
        float* full_dst = (s == NSTEPS - 1) ? out : p_hfull;
        step_kernel<<<grid, NT, S_SMEM_TOTAL>>>(h16_in, p_whhhi,
                                                p_ihb, p_hfull, tau,
                                                full_dst, h16_out, HDIM);
        __half* t16 = h16_in; h16_in = h16_out; h16_out = t16;
    }
}